// round 16
// baseline (speedup 1.0000x reference)
#include <cuda_runtime.h>
#include <cuda_fp16.h>
#include <cstdint>

#define MT 128
#define NT 128
#define K_DIM 8192
#define N_DIM 512
#define M_DIM 8192
#define CHUNKS (K_DIM / 64)       // 64 k-elements (128B fp16) per chunk
#define THREADS 256
#define STAGES 3

#define SM_BIAS   0
#define SM_TILES  1024
#define A_OFF     0
#define B_OFF     (MT * 128)                 // 16384
#define STAGE_BYTES ((MT + NT) * 128)        // 32768
#define SMEM_TOTAL (SM_TILES + STAGES * STAGE_BYTES)  // 99328 -> 2 CTAs/SM

// hashed-gathered fp16 weight [512][8192] (8 MB, L2-resident)
__device__ __half g_wh[(size_t)N_DIM * K_DIM];

// ---------------- helpers ----------------
__device__ __forceinline__ uint32_t smem_u32(const void* p) {
    uint32_t a;
    asm("{ .reg .u64 t; cvta.to.shared.u64 t, %1; cvt.u32.u64 %0, t; }" : "=r"(a) : "l"(p));
    return a;
}
__device__ __forceinline__ uint32_t swz(uint32_t o) { return o ^ ((o >> 3) & 0x70); }

__device__ __forceinline__ void cp16(uint32_t dst, const void* src) {
    asm volatile("cp.async.cg.shared.global [%0], [%1], 16;" :: "r"(dst), "l"(src) : "memory");
}

__device__ __forceinline__ void ldsm4(uint32_t* r, uint32_t addr) {
    asm volatile("ldmatrix.sync.aligned.m8n8.x4.shared.b16 {%0,%1,%2,%3}, [%4];"
                 : "=r"(r[0]), "=r"(r[1]), "=r"(r[2]), "=r"(r[3]) : "r"(addr));
}

__device__ __forceinline__ void mma16(float* c, const uint32_t* a, const uint32_t* b) {
    asm volatile(
        "mma.sync.aligned.m16n8k16.row.col.f32.f16.f16.f32 "
        "{%0,%1,%2,%3}, {%4,%5,%6,%7}, {%8,%9}, {%0,%1,%2,%3};"
        : "+f"(c[0]), "+f"(c[1]), "+f"(c[2]), "+f"(c[3])
        : "r"(a[0]), "r"(a[1]), "r"(a[2]), "r"(a[3]), "r"(b[0]), "r"(b[1]));
}

// ---------------- prekernel: hashed gather of w -> fp16 ----------------
__global__ void gather_w(const float* __restrict__ w, const int* __restrict__ rn) {
    const uint32_t r0 = (uint32_t)rn[0], r1 = (uint32_t)rn[1],
                   r2 = (uint32_t)rn[2], r3 = (uint32_t)rn[3];
    int gid = blockIdx.x * 256 + threadIdx.x;     // [0, 512*8192/4)
    int n = gid >> 11;                            // / 2048
    int k = (gid & 2047) << 2;
    uint32_t kb = (uint32_t)(k >> 5), nb = (uint32_t)(n >> 5);
    uint32_t h = ((kb * r0 + nb * r1 + r2) ^ r3) % 32u;
    const float4 v = *(const float4*)(w + n * 1024 + h * 32u + (k & 31));
    __half2 h0 = __floats2half2_rn(v.x, v.y);
    __half2 h1 = __floats2half2_rn(v.z, v.w);
    uint2 o;
    o.x = *(uint32_t*)&h0;
    o.y = *(uint32_t*)&h1;
    *(uint2*)(g_wh + (size_t)n * K_DIM + k) = o;
}

// ---------------- main GEMM (fp32 x converted inline, fp16 HMMA, fp32 accum) ----
__global__ void __launch_bounds__(THREADS, 2)
ssl_gemm(const float* __restrict__ x, const float* __restrict__ bias, float* __restrict__ out) {
    extern __shared__ char smem[];
    const uint32_t sb = smem_u32(smem);
    const int tid = threadIdx.x;
    const int lane = tid & 31, wid = tid >> 5;
    const int wm = (wid & 1) * 64;       // 2 warp-rows of 64
    const int wn = (wid >> 1) * 32;      // 4 warp-cols of 32
    const int g = lane >> 2, t = lane & 3;
    const int m0 = blockIdx.y * MT, n0 = blockIdx.x * NT;

    // ldmatrix per-thread selectors (one k16 step = 32 bytes)
    const int a_row = lane & 15;
    const int a_kb  = (lane >> 4) << 4;
    const int b_row = (lane & 7) + ((lane >> 4) << 3);
    const int b_kb  = ((lane >> 3) & 1) << 4;

    if (tid < 64)
        ((float2*)(smem + SM_BIAS))[tid] = ((const float2*)(bias + n0))[tid];

    float acc[4][4][4];
    #pragma unroll
    for (int i = 0; i < 4; i++)
        #pragma unroll
        for (int j = 0; j < 4; j++)
            #pragma unroll
            for (int q = 0; q < 4; q++) acc[i][j][q] = 0.f;

    const float*  xP = x + (size_t)m0 * K_DIM;
    const __half* bP = g_wh + (size_t)n0 * K_DIM;

    // ---- A producer: LDG fp32 -> cvt -> STS fp16 (half-batches of 2 granules) ----
    // granule i in [0,1024): row = i>>3 (0..127), c = i&7 (16B fp16 = 8 halves = 32B fp32)
    auto lda2 = [&](int kc, int jbase, float4* ra) {
        const int k0 = kc * 64;
        #pragma unroll
        for (int j = 0; j < 2; j++) {
            int i = (jbase + j) * THREADS + tid, row = i >> 3, c = i & 7;
            const float* s = xP + (size_t)row * K_DIM + k0 + c * 8;
            ra[2 * j]     = *(const float4*)s;
            ra[2 * j + 1] = *(const float4*)(s + 4);
        }
    };
    auto sta2 = [&](int kc, int jbase, const float4* ra) {
        const uint32_t base = sb + SM_TILES + (uint32_t)(kc % STAGES) * STAGE_BYTES + A_OFF;
        #pragma unroll
        for (int j = 0; j < 2; j++) {
            int i = (jbase + j) * THREADS + tid, row = i >> 3, c = i & 7;
            __half2 h0 = __floats2half2_rn(ra[2 * j].x,     ra[2 * j].y);
            __half2 h1 = __floats2half2_rn(ra[2 * j].z,     ra[2 * j].w);
            __half2 h2 = __floats2half2_rn(ra[2 * j + 1].x, ra[2 * j + 1].y);
            __half2 h3 = __floats2half2_rn(ra[2 * j + 1].z, ra[2 * j + 1].w);
            asm volatile("st.shared.v4.b32 [%0], {%1,%2,%3,%4};"
                :: "r"(base + swz((uint32_t)(row * 128 + c * 16))),
                   "r"(*(uint32_t*)&h0), "r"(*(uint32_t*)&h1),
                   "r"(*(uint32_t*)&h2), "r"(*(uint32_t*)&h3) : "memory");
        }
    };
    auto loadB = [&](int kc) {
        const uint32_t base = sb + SM_TILES + (uint32_t)(kc % STAGES) * STAGE_BYTES + B_OFF;
        const int k0 = kc * 64;
        #pragma unroll
        for (int j = 0; j < 4; j++) {       // B: 128 rows x 8 x 16B
            int i = j * THREADS + tid, row = i >> 3, c = i & 7;
            cp16(base + swz((uint32_t)(row * 128 + c * 16)),
                 bP + (size_t)row * K_DIM + k0 + c * 8);
        }
    };

    // one k16 step of MMAs from stage sA/sB
    auto compute_ks = [&](uint32_t sA, uint32_t sB, int ks) {
        const int kbyte = ks * 32;
        uint32_t af[4][4], bf[2][4];
        #pragma unroll
        for (int mi = 0; mi < 4; mi++)
            ldsm4(af[mi], sA + swz((uint32_t)((wm + mi * 16 + a_row) * 128 + kbyte + a_kb)));
        #pragma unroll
        for (int np = 0; np < 2; np++)
            ldsm4(bf[np], sB + swz((uint32_t)((wn + np * 16 + b_row) * 128 + kbyte + b_kb)));
        #pragma unroll
        for (int mi = 0; mi < 4; mi++)
            #pragma unroll
            for (int np = 0; np < 2; np++) {
                mma16(acc[mi][2 * np],     af[mi], &bf[np][0]);
                mma16(acc[mi][2 * np + 1], af[mi], &bf[np][2]);
            }
    };

    // prologue: stage chunks 0 and 1
    {
        float4 r[4];
        lda2(0, 0, r); sta2(0, 0, r); lda2(0, 2, r); sta2(0, 2, r);
        lda2(1, 0, r); sta2(1, 0, r); lda2(1, 2, r); sta2(1, 2, r);
    }
    loadB(0); asm volatile("cp.async.commit_group;" ::: "memory");
    loadB(1); asm volatile("cp.async.commit_group;" ::: "memory");

    #pragma unroll 1
    for (int kc = 0; kc < CHUNKS; kc++) {
        asm volatile("cp.async.wait_group 1;" ::: "memory");
        __syncthreads();   // publishes chunk kc (A STS + B cp.async); orders compute(kc-1)
                           // before the overwrite of stage (kc+2)%3 == (kc-1)%3 below
        const bool pf = (kc + 2 < CHUNKS);
        float4 ra[4];
        if (pf) { lda2(kc + 2, 0, ra); loadB(kc + 2); }
        asm volatile("cp.async.commit_group;" ::: "memory");

        const uint32_t sA = sb + SM_TILES + (uint32_t)(kc % STAGES) * STAGE_BYTES + A_OFF;
        const uint32_t sB = sA + (B_OFF - A_OFF);

        compute_ks(sA, sB, 0);
        compute_ks(sA, sB, 1);
        if (pf) { sta2(kc + 2, 0, ra); lda2(kc + 2, 2, ra); }   // LDG latency hid by ks0-1
        compute_ks(sA, sB, 2);
        compute_ks(sA, sB, 3);
        if (pf) sta2(kc + 2, 2, ra);                            // hid by ks2-3
    }

    // epilogue: bias + store
    const float* bs = (const float*)(smem + SM_BIAS);
    #pragma unroll
    for (int mi = 0; mi < 4; mi++) {
        const int r0 = m0 + wm + mi * 16 + g;
        #pragma unroll
        for (int ni = 0; ni < 4; ni++) {
            const int col = wn + ni * 8 + 2 * t;
            float2 v0, v1;
            v0.x = acc[mi][ni][0] + bs[col];
            v0.y = acc[mi][ni][1] + bs[col + 1];
            v1.x = acc[mi][ni][2] + bs[col];
            v1.y = acc[mi][ni][3] + bs[col + 1];
            *(float2*)(out + (size_t)r0 * N_DIM + n0 + col) = v0;
            *(float2*)(out + (size_t)(r0 + 8) * N_DIM + n0 + col) = v1;
        }
    }
}

extern "C" void kernel_launch(void* const* d_in, const int* in_sizes, int n_in,
                              void* d_out, int out_size) {
    (void)in_sizes; (void)n_in; (void)out_size;
    const float* x    = (const float*)d_in[0];
    const float* w    = (const float*)d_in[1];
    const float* bias = (const float*)d_in[2];
    const int*   rn   = (const int*)d_in[3];
    float* out = (float*)d_out;

    gather_w<<<(N_DIM * K_DIM / 4) / 256, 256>>>(w, rn);

    cudaFuncSetAttribute(ssl_gemm, cudaFuncAttributeMaxDynamicSharedMemorySize, SMEM_TOTAL);
    ssl_gemm<<<dim3(N_DIM / NT, M_DIM / MT), THREADS, SMEM_TOTAL>>>(x, bias, out);
}